// round 16
// baseline (speedup 1.0000x reference)
#include <cuda_runtime.h>
#include <cuda_fp16.h>
#include <math.h>
#include <stdint.h>

#define Bb 2
#define Ss 2048
#define Dd 1024
#define Hh 16
#define Mm 4096

// ---------------------------------------------------------------------------
// Scratch (device globals), fp16
// ---------------------------------------------------------------------------
__device__ __half g_xq[Mm*Dd], g_xk[Mm*Dd], g_xv[Mm*Dd];      // inputs, plain
__device__ __half g_wqh[Dd*Dd], g_wql[Dd*Dd];
__device__ __half g_wkh[Dd*Dd], g_wkl[Dd*Dd];
__device__ __half g_wvh[Dd*Dd], g_wvl[Dd*Dd];
__device__ __half g_woh[Dd*Dd], g_wol[Dd*Dd];
__device__ __half g_q[Mm*Dd], g_k[Mm*Dd], g_v[Mm*Dd];          // q,k,v plain
__device__ __half g_c[Mm*Dd];                                  // ctx plain
__device__ float  g_pm[(size_t)Bb*Ss*Ss];                      // masked posr fp32

// ---------------------------------------------------------------------------
// Helpers
// ---------------------------------------------------------------------------
__device__ __forceinline__ uint32_t smem_u32(const void* p) {
    return (uint32_t)__cvta_generic_to_shared(p);
}
__device__ __forceinline__ void cp16(uint32_t dst, const void* src) {
    asm volatile("cp.async.cg.shared.global [%0], [%1], 16;\n" :: "r"(dst), "l"(src));
}
#define CP_COMMIT() asm volatile("cp.async.commit_group;\n" ::: "memory")
template<int N> __device__ __forceinline__ void cp_wait() {
    asm volatile("cp.async.wait_group %0;\n" :: "n"(N) : "memory");
}
__device__ __forceinline__ void ldmx4(uint32_t& r0, uint32_t& r1, uint32_t& r2, uint32_t& r3, uint32_t a) {
    asm volatile("ldmatrix.sync.aligned.m8n8.x4.shared.b16 {%0,%1,%2,%3}, [%4];\n"
        : "=r"(r0), "=r"(r1), "=r"(r2), "=r"(r3) : "r"(a));
}
__device__ __forceinline__ void ldmx4t(uint32_t& r0, uint32_t& r1, uint32_t& r2, uint32_t& r3, uint32_t a) {
    asm volatile("ldmatrix.sync.aligned.m8n8.x4.trans.shared.b16 {%0,%1,%2,%3}, [%4];\n"
        : "=r"(r0), "=r"(r1), "=r"(r2), "=r"(r3) : "r"(a));
}
__device__ __forceinline__ void mma16816(float* c, uint32_t a0, uint32_t a1, uint32_t a2, uint32_t a3,
                                         uint32_t b0, uint32_t b1) {
    asm volatile("mma.sync.aligned.m16n8k16.row.col.f32.f16.f16.f32 "
        "{%0,%1,%2,%3}, {%4,%5,%6,%7}, {%8,%9}, {%0,%1,%2,%3};\n"
        : "+f"(c[0]), "+f"(c[1]), "+f"(c[2]), "+f"(c[3])
        : "r"(a0), "r"(a1), "r"(a2), "r"(a3), "r"(b0), "r"(b1));
}
__device__ __forceinline__ uint32_t pack_h(float e0, float e1) {
    union { __half2 v; uint32_t u; } t;
    t.v = __floats2half2_rn(e0, e1);
    return t.u;
}
__device__ __forceinline__ float lo_h(uint32_t p) {
    union { uint32_t u; __half2 v; } t; t.u = p; return __low2float(t.v);
}
__device__ __forceinline__ float hi_h(uint32_t p) {
    union { uint32_t u; __half2 v; } t; t.u = p; return __high2float(t.v);
}

// exp via MUFU ex2.approx (underflows to 0 for very negative x)
__device__ __forceinline__ float fast_exp(float x) {
    float y = x * 1.4426950408889634f;
    float r;
    asm("ex2.approx.f32 %0, %1;\n" : "=f"(r) : "f"(y));
    return r;
}

// swizzled smem byte offset within a tile of 128B rows (8 chunks of 16B)
__device__ __forceinline__ uint32_t swz(int row, int chunk) {
    return (uint32_t)(row * 128 + ((chunk ^ (row & 7)) << 4));
}

// ---------------------------------------------------------------------------
// Preprocess, single launch.
// ---------------------------------------------------------------------------
__global__ void pre_all(const float4* __restrict__ Q, const float4* __restrict__ K,
                        const float4* __restrict__ V,
                        const float4* __restrict__ W0, const float4* __restrict__ W1,
                        const float4* __restrict__ W2, const float4* __restrict__ W3,
                        uint32_t* __restrict__ Qo, uint32_t* __restrict__ Ko, uint32_t* __restrict__ Vo,
                        uint32_t* __restrict__ W0h, uint32_t* __restrict__ W0l,
                        uint32_t* __restrict__ W1h, uint32_t* __restrict__ W1l,
                        uint32_t* __restrict__ W2h, uint32_t* __restrict__ W2l,
                        uint32_t* __restrict__ W3h, uint32_t* __restrict__ W3l)
{
    int y = blockIdx.y;
    if (y < 3) {
        int idx = blockIdx.x * 256 + threadIdx.x;
        const float4* X = (y == 0) ? Q : (y == 1) ? K : V;
        uint32_t*     O = (y == 0) ? Qo : (y == 1) ? Ko : Vo;
        float4 v = X[idx];
        O[idx*2]   = pack_h(v.x, v.y);
        O[idx*2+1] = pack_h(v.z, v.w);
    } else {
        if (blockIdx.x >= Dd) return;
        int idx = blockIdx.x * 256 + threadIdx.x;
        const float4* X = (y == 3) ? W0 : (y == 4) ? W1 : (y == 5) ? W2 : W3;
        uint32_t* Xh = (y == 3) ? W0h : (y == 4) ? W1h : (y == 5) ? W2h : W3h;
        uint32_t* Xl = (y == 3) ? W0l : (y == 4) ? W1l : (y == 5) ? W2l : W3l;
        float4 v = X[idx];
        uint32_t h0 = pack_h(v.x, v.y);
        uint32_t l0 = pack_h(v.x - lo_h(h0), v.y - hi_h(h0));
        uint32_t h1 = pack_h(v.z, v.w);
        uint32_t l1 = pack_h(v.z - lo_h(h1), v.w - hi_h(h1));
        Xh[idx*2]   = h0;  Xh[idx*2+1] = h1;
        Xl[idx*2]   = l0;  Xl[idx*2+1] = l1;
    }
}

// Fold mask into posr: pm = mask ? posr : -1e9
__global__ void pre_mask(const float4* __restrict__ P, const int4* __restrict__ Mk,
                         float4* __restrict__ Pm)
{
    size_t idx = (size_t)blockIdx.x * 256 + threadIdx.x;
    size_t e0 = idx * 4;
    int b   = (int)(e0 / ((size_t)Ss * Ss));
    int col = (int)(e0 % Ss);
    float4 v = P[idx];
    int4 mk = Mk[(b * Ss + col) >> 2];
    v.x = (mk.x != 0) ? v.x : -1e9f;
    v.y = (mk.y != 0) ? v.y : -1e9f;
    v.z = (mk.z != 0) ? v.z : -1e9f;
    v.w = (mk.w != 0) ? v.w : -1e9f;
    Pm[idx] = v;
}

// ---------------------------------------------------------------------------
// fp16 2-pass GEMM core (unchanged)
// ---------------------------------------------------------------------------
#define GST 65536
#define GSMEM (3*GST)

__device__ __forceinline__ void gemm_load_stage(uint32_t base,
    const __half* A, const __half* Wh, const __half* Wl,
    int m0, int n0, int k0, int tid)
{
#pragma unroll
    for (int i = 0; i < 4; i++) {
        int idx = tid + i * 512;
        int r = idx >> 3, c = idx & 7;
        cp16(base + swz(r, c), A + (size_t)(m0 + r) * Dd + k0 + c * 8);
    }
#pragma unroll
    for (int i = 0; i < 2; i++) {
        int idx = tid + i * 512;
        int r = idx >> 3, c = idx & 7;
        uint32_t so = swz(r, c);
        cp16(base + 32768 + so, Wh + (size_t)(n0 + r) * Dd + k0 + c * 8);
        cp16(base + 49152 + so, Wl + (size_t)(n0 + r) * Dd + k0 + c * 8);
    }
}

template<int OUTMODE>
__device__ __forceinline__ void gemm_core(
    const __half* __restrict__ A,
    const __half* __restrict__ Wh, const __half* __restrict__ Wl,
    const float* __restrict__ bias,
    float* __restrict__ Cf, uint32_t* __restrict__ Co)
{
    extern __shared__ __align__(16) char sm[];
    const uint32_t smb = smem_u32(sm);
    const int tid = threadIdx.x, wid = tid >> 5, lane = tid & 31;
    const int m0 = blockIdx.y * 256, n0 = blockIdx.x * 128;
    const int wm = wid >> 2, wn = wid & 3;
    const int sub = lane >> 3, lr = lane & 7;

    float acc[4][4][4];
#pragma unroll
    for (int a = 0; a < 4; a++)
#pragma unroll
        for (int b = 0; b < 4; b++)
#pragma unroll
            for (int c = 0; c < 4; c++) acc[a][b][c] = 0.f;

    gemm_load_stage(smb,       A, Wh, Wl, m0, n0, 0,  tid); CP_COMMIT();
    gemm_load_stage(smb + GST, A, Wh, Wl, m0, n0, 64, tid); CP_COMMIT();

    for (int it = 0; it < 16; it++) {
        if (it + 2 < 16) {
            gemm_load_stage(smb + ((it+2)%3)*GST, A, Wh, Wl, m0, n0, (it+2)*64, tid);
            CP_COMMIT();
            cp_wait<2>();
        } else {
            cp_wait<0>();
        }
        __syncthreads();
        uint32_t stg = smb + (it%3)*GST;

#pragma unroll
        for (int ks = 0; ks < 4; ks++) {
            int ch = 2*ks + (sub >> 1);
            uint32_t ah[4][4];
#pragma unroll
            for (int mt = 0; mt < 4; mt++) {
                int row = wm*64 + mt*16 + lr + (sub & 1)*8;
                ldmx4(ah[mt][0], ah[mt][1], ah[mt][2], ah[mt][3], stg + swz(row, ch));
            }
            uint32_t bh[8], bl[8];
#pragma unroll
            for (int p = 0; p < 2; p++) {
                int row = wn*32 + p*16 + lr + (sub & 1)*8;
                uint32_t so = swz(row, ch);
                ldmx4(bh[p*4+0], bh[p*4+1], bh[p*4+2], bh[p*4+3], stg + 32768 + so);
                ldmx4(bl[p*4+0], bl[p*4+1], bl[p*4+2], bl[p*4+3], stg + 49152 + so);
            }
#pragma unroll
            for (int mt = 0; mt < 4; mt++)
#pragma unroll
                for (int p = 0; p < 2; p++) {
                    mma16816(acc[mt][2*p],   ah[mt][0],ah[mt][1],ah[mt][2],ah[mt][3], bh[p*4+0], bh[p*4+2]);
                    mma16816(acc[mt][2*p+1], ah[mt][0],ah[mt][1],ah[mt][2],ah[mt][3], bh[p*4+1], bh[p*4+3]);
                }
#pragma unroll
            for (int mt = 0; mt < 4; mt++)
#pragma unroll
                for (int p = 0; p < 2; p++) {
                    mma16816(acc[mt][2*p],   ah[mt][0],ah[mt][1],ah[mt][2],ah[mt][3], bl[p*4+0], bl[p*4+2]);
                    mma16816(acc[mt][2*p+1], ah[mt][0],ah[mt][1],ah[mt][2],ah[mt][3], bl[p*4+1], bl[p*4+3]);
                }
        }
        __syncthreads();
    }

#pragma unroll
    for (int mt = 0; mt < 4; mt++) {
#pragma unroll
        for (int nt = 0; nt < 4; nt++) {
            int gr = m0 + wm*64 + mt*16 + (lane >> 2);
            int gc = n0 + wn*32 + nt*8 + (lane & 3)*2;
            float b0 = bias[gc], b1 = bias[gc+1];
            float v0 = acc[mt][nt][0] + b0, v1 = acc[mt][nt][1] + b1;
            float v2 = acc[mt][nt][2] + b0, v3 = acc[mt][nt][3] + b1;
            if (OUTMODE == 0) {
                *(float2*)(Cf + (size_t)gr*Dd + gc)     = make_float2(v0, v1);
                *(float2*)(Cf + (size_t)(gr+8)*Dd + gc) = make_float2(v2, v3);
            } else {
                Co[(size_t)gr*512 + (gc>>1)]     = pack_h(v0, v1);
                Co[(size_t)(gr+8)*512 + (gc>>1)] = pack_h(v2, v3);
            }
        }
    }
}

struct QKVArgs {
    const __half* A[3];
    const __half* Wh[3];
    const __half* Wl[3];
    const float*  bias[3];
    uint32_t*     Co[3];
};

__global__ __launch_bounds__(512) void gemm_qkv(QKVArgs a)
{
    int z = blockIdx.z;
    gemm_core<1>(a.A[z], a.Wh[z], a.Wl[z], a.bias[z], nullptr, a.Co[z]);
}

__global__ __launch_bounds__(512) void gemm_out(
    const __half* __restrict__ A,
    const __half* __restrict__ Wh, const __half* __restrict__ Wl,
    const float* __restrict__ bias, float* __restrict__ Cf)
{
    gemm_core<0>(A, Wh, Wl, bias, Cf, nullptr);
}

// ---------------------------------------------------------------------------
// Flash attention, plain fp16, NO-MAX softmax. CTA = 128 q-rows, 4 warps x 32.
// k-tile processed in two 32-column halves to halve S live registers
// (peak regs ~175 -> no spills at 2 CTAs/SM). Pre-masked posr fp32.
// ---------------------------------------------------------------------------
#define AQ 0
#define AKV 16384              // stage: K 8K | V 8K
#define AKVST 16384
#define ASMEM (AKV + 2*AKVST)  // 49152

__device__ __forceinline__ void attn_load_kv(uint32_t base,
    const __half* K, const __half* V,
    size_t rowBase, int headOff, int k0, int tid)
{
#pragma unroll
    for (int i = 0; i < 4; i++) {
        int idx = tid + i * 128;          // 0..511 : 64 rows x 8 chunks
        int r = idx >> 3, c = idx & 7;
        uint32_t so = swz(r, c);
        size_t g = (rowBase + k0 + r) * Dd + headOff + c * 8;
        cp16(base + so,        K + g);
        cp16(base + 8192 + so, V + g);
    }
}

__global__ __launch_bounds__(128, 2) void attn_kernel(
    const __half* __restrict__ Q,
    const __half* __restrict__ K, const __half* __restrict__ V,
    uint32_t* __restrict__ Co,
    const float* __restrict__ pm)
{
    extern __shared__ __align__(16) char sm[];
    const uint32_t smb = smem_u32(sm);
    const int tid = threadIdx.x, wid = tid >> 5, lane = tid & 31;
    const int sub = lane >> 3, lr = lane & 7;
    const int q0 = blockIdx.x * 128;
    const int h  = blockIdx.y;
    const int b  = blockIdx.z;
    const int headOff = h * 64;
    const size_t rowBase = (size_t)b * Ss;

    // load Q tile (128 x 64 fp16)
#pragma unroll
    for (int i = 0; i < 8; i++) {
        int idx = tid + i * 128;          // 0..1023
        int r = idx >> 3, c = idx & 7;
        cp16(smb + AQ + swz(r, c), Q + (rowBase + q0 + r) * Dd + headOff + c * 8);
    }
    attn_load_kv(smb + AKV, K, V, rowBase, headOff, 0, tid);
    CP_COMMIT();
    cp_wait<0>();
    __syncthreads();

    // preload Q fragments: warp owns rows [wid*32, wid*32+32), 2 m-tiles
    uint32_t qf[4][2][4];
#pragma unroll
    for (int ks = 0; ks < 4; ks++) {
        int ch = 2*ks + (sub >> 1);
#pragma unroll
        for (int mt = 0; mt < 2; mt++) {
            int row = wid*32 + mt*16 + lr + (sub & 1)*8;
            ldmx4(qf[ks][mt][0], qf[ks][mt][1], qf[ks][mt][2], qf[ks][mt][3],
                  smb + AQ + swz(row, ch));
        }
    }

    float o[2][8][4];
#pragma unroll
    for (int mt = 0; mt < 2; mt++)
#pragma unroll
        for (int i = 0; i < 8; i++)
#pragma unroll
            for (int j = 0; j < 4; j++) o[mt][i][j] = 0.f;
    float lrow[4] = {0.f, 0.f, 0.f, 0.f};

    const int rq = wid*32 + (lane >> 2);
    const float* pr[4];
    pr[0] = pm + ((size_t)b*Ss + q0 + rq)*Ss;
    pr[1] = pr[0] + 8*Ss;
    pr[2] = pr[0] + 16*Ss;
    pr[3] = pr[0] + 24*Ss;

    for (int kt = 0; kt < 32; kt++) {
        uint32_t stg = smb + AKV + (kt & 1) * AKVST;
        if (kt + 1 < 32) {
            attn_load_kv(smb + AKV + ((kt+1) & 1) * AKVST, K, V,
                         rowBase, headOff, (kt+1)*64, tid);
            CP_COMMIT();
            cp_wait<1>();
        } else {
            cp_wait<0>();
        }
        __syncthreads();

        // process k-tile in two 32-column halves (halves S live range)
#pragma unroll
        for (int hf = 0; hf < 2; hf++) {
            // ---- S half = Q @ K^T over key cols [hf*32, hf*32+32) ----
            float s[2][4][4];
#pragma unroll
            for (int mt = 0; mt < 2; mt++)
#pragma unroll
                for (int i = 0; i < 4; i++)
#pragma unroll
                    for (int j = 0; j < 4; j++) s[mt][i][j] = 0.f;

#pragma unroll
            for (int ks = 0; ks < 4; ks++) {
                int ch = 2*ks + (sub >> 1);
#pragma unroll
                for (int pl = 0; pl < 2; pl++) {          // local n-tile pair
                    int row = hf*32 + pl*16 + lr + (sub & 1)*8;
                    uint32_t kh4[4];
                    ldmx4(kh4[0], kh4[1], kh4[2], kh4[3], stg + swz(row, ch));
#pragma unroll
                    for (int mt = 0; mt < 2; mt++) {
                        mma16816(s[mt][2*pl],   qf[ks][mt][0],qf[ks][mt][1],qf[ks][mt][2],qf[ks][mt][3], kh4[0], kh4[2]);
                        mma16816(s[mt][2*pl+1], qf[ks][mt][0],qf[ks][mt][1],qf[ks][mt][2],qf[ks][mt][3], kh4[1], kh4[3]);
                    }
                }
            }

            // ---- p = exp(s*0.125 + pm); accumulate row sums ----
            const int colB = kt*64 + hf*32 + (lane & 3)*2;
            uint32_t P[2][2][4];   // [ksl][mt][frag]
#pragma unroll
            for (int mt = 0; mt < 2; mt++) {
#pragma unroll
                for (int nt = 0; nt < 4; nt++) {
                    int col = colB + nt*8;
                    float2 p0 = *(const float2*)(pr[2*mt]   + col);
                    float2 p1 = *(const float2*)(pr[2*mt+1] + col);
                    float e0 = fast_exp(fmaf(s[mt][nt][0], 0.125f, p0.x));
                    float e1 = fast_exp(fmaf(s[mt][nt][1], 0.125f, p0.y));
                    float e2 = fast_exp(fmaf(s[mt][nt][2], 0.125f, p1.x));
                    float e3 = fast_exp(fmaf(s[mt][nt][3], 0.125f, p1.y));
                    lrow[2*mt]   += e0 + e1;
                    lrow[2*mt+1] += e2 + e3;
                    int ksl = nt >> 1, half = nt & 1;
                    P[ksl][mt][2*half]   = pack_h(e0, e1);
                    P[ksl][mt][2*half+1] = pack_h(e2, e3);
                }
            }

            // ---- acc += P @ V (V rows hf*32 .. hf*32+32) ----
#pragma unroll
            for (int ksl = 0; ksl < 2; ksl++) {
                int row = hf*32 + ksl*16 + (lane & 15);
#pragma unroll
                for (int np = 0; np < 4; np++) {
                    uint32_t so = swz(row, np*2 + (lane >> 4));
                    uint32_t h0,h1,h2,h3;
                    ldmx4t(h0,h1,h2,h3, stg + 8192 + so);
#pragma unroll
                    for (int mt = 0; mt < 2; mt++) {
                        mma16816(o[mt][2*np],   P[ksl][mt][0],P[ksl][mt][1],P[ksl][mt][2],P[ksl][mt][3], h0,h1);
                        mma16816(o[mt][2*np+1], P[ksl][mt][0],P[ksl][mt][1],P[ksl][mt][2],P[ksl][mt][3], h2,h3);
                    }
                }
            }
        }
        __syncthreads();
    }

    // ---- epilogue: single row-sum reduction, normalize, write ctx ----
    float inv[4];
#pragma unroll
    for (int r = 0; r < 4; r++) {
        lrow[r] += __shfl_xor_sync(0xffffffffu, lrow[r], 1);
        lrow[r] += __shfl_xor_sync(0xffffffffu, lrow[r], 2);
        inv[r] = 1.f / lrow[r];
    }
#pragma unroll
    for (int mt = 0; mt < 2; mt++) {
        const size_t gr0 = rowBase + (size_t)(q0 + rq + mt*16);
        const size_t gr1 = gr0 + 8;
#pragma unroll
        for (int nt = 0; nt < 8; nt++) {
            int gc = headOff + nt*8 + (lane & 3)*2;
            Co[gr0*512 + (gc>>1)] = pack_h(o[mt][nt][0] * inv[2*mt],   o[mt][nt][1] * inv[2*mt]);
            Co[gr1*512 + (gc>>1)] = pack_h(o[mt][nt][2] * inv[2*mt+1], o[mt][nt][3] * inv[2*mt+1]);
        }
    }
}

// ---------------------------------------------------------------------------
extern "C" void kernel_launch(void* const* d_in, const int* in_sizes, int n_in,
                              void* d_out, int out_size)
{
    const float* query = (const float*)d_in[0];
    const float* key   = (const float*)d_in[1];
    const float* value = (const float*)d_in[2];
    const int*   mask  = (const int*)  d_in[3];
    const float* posr  = (const float*)d_in[4];
    const float* Wq    = (const float*)d_in[5];
    const float* bq    = (const float*)d_in[6];
    const float* Wk    = (const float*)d_in[7];
    const float* bk    = (const float*)d_in[8];
    const float* Wv    = (const float*)d_in[9];
    const float* bv    = (const float*)d_in[10];
    const float* Wo    = (const float*)d_in[11];
    const float* bo    = (const float*)d_in[12];
    float* out = (float*)d_out;

    __half *xq,*xk,*xv, *q16,*k16,*v16, *c16;
    __half *wqh,*wql,*wkh,*wkl,*wvh,*wvl,*woh,*wol;
    float *pmreal;
    cudaGetSymbolAddress((void**)&xq, g_xq);   cudaGetSymbolAddress((void**)&xk, g_xk);
    cudaGetSymbolAddress((void**)&xv, g_xv);
    cudaGetSymbolAddress((void**)&wqh, g_wqh); cudaGetSymbolAddress((void**)&wql, g_wql);
    cudaGetSymbolAddress((void**)&wkh, g_wkh); cudaGetSymbolAddress((void**)&wkl, g_wkl);
    cudaGetSymbolAddress((void**)&wvh, g_wvh); cudaGetSymbolAddress((void**)&wvl, g_wvl);
    cudaGetSymbolAddress((void**)&woh, g_woh); cudaGetSymbolAddress((void**)&wol, g_wol);
    cudaGetSymbolAddress((void**)&q16, g_q);   cudaGetSymbolAddress((void**)&k16, g_k);
    cudaGetSymbolAddress((void**)&v16, g_v);
    cudaGetSymbolAddress((void**)&c16, g_c);
    cudaGetSymbolAddress((void**)&pmreal, g_pm);

    pre_all<<<dim3(Mm, 7), 256>>>(
        (const float4*)query, (const float4*)key, (const float4*)value,
        (const float4*)Wq, (const float4*)Wk, (const float4*)Wv, (const float4*)Wo,
        (uint32_t*)xq, (uint32_t*)xk, (uint32_t*)xv,
        (uint32_t*)wqh, (uint32_t*)wql, (uint32_t*)wkh, (uint32_t*)wkl,
        (uint32_t*)wvh, (uint32_t*)wvl, (uint32_t*)woh, (uint32_t*)wol);

    pre_mask<<<((size_t)Bb*Ss*Ss/4)/256, 256>>>(
        (const float4*)posr, (const int4*)mask, (float4*)pmreal);

    cudaFuncSetAttribute(gemm_qkv, cudaFuncAttributeMaxDynamicSharedMemorySize, GSMEM);
    cudaFuncSetAttribute(gemm_out, cudaFuncAttributeMaxDynamicSharedMemorySize, GSMEM);
    cudaFuncSetAttribute(attn_kernel, cudaFuncAttributeMaxDynamicSharedMemorySize, ASMEM);

    QKVArgs qa;
    qa.A[0] = xq;  qa.A[1] = xk;  qa.A[2] = xv;
    qa.Wh[0] = wqh; qa.Wh[1] = wkh; qa.Wh[2] = wvh;
    qa.Wl[0] = wql; qa.Wl[1] = wkl; qa.Wl[2] = wvl;
    qa.bias[0] = bq; qa.bias[1] = bk; qa.bias[2] = bv;
    qa.Co[0] = (uint32_t*)q16; qa.Co[1] = (uint32_t*)k16; qa.Co[2] = (uint32_t*)v16;
    gemm_qkv<<<dim3(Dd/128, Mm/256, 3), 512, GSMEM>>>(qa);

    attn_kernel<<<dim3(Ss/128, Hh, Bb), 128, ASMEM>>>(q16, k16, v16,
        (uint32_t*)c16, pmreal);

    gemm_out<<<dim3(Dd/128, Mm/256), 512, GSMEM>>>(c16, woh, wol, bo, out);
}